// round 1
// baseline (speedup 1.0000x reference)
#include <cuda_runtime.h>
#include <math.h>
#include <limits.h>

// Problem constants (shapes fixed by setup_inputs)
#define HDIM 128
#define SDIM 32
#define KTOP 8
#define CMAX 100000
#define NB1  128   // stage-1 top-k blocks

// Scratch (no device allocation allowed -> __device__ globals)
__device__ float g_sims[CMAX];
__device__ float g_cand_v[NB1 * KTOP];
__device__ int   g_cand_i[NB1 * KTOP];
__device__ float g_top_v[KTOP];
__device__ int   g_top_i[KTOP];

__device__ __forceinline__ bool better(float va, int ia, float vb, int ib) {
    // strict ordering matching jax.lax.top_k: higher value first, ties -> lower index
    return (va > vb) || (va == vb && ia < ib);
}

// ---------------------------------------------------------------------------
// Kernel A: cosine similarity of query row 0 vs all embeddings.
// One warp per embedding; each lane holds a float4 (128 floats / 32 lanes).
// Fully coalesced 512B reads per warp -> HBM streaming bound.
// ---------------------------------------------------------------------------
__global__ void sims_kernel(const float* __restrict__ q,
                            const float* __restrict__ emb,
                            int C) {
    const int lane = threadIdx.x & 31;
    const int warp = (blockIdx.x * blockDim.x + threadIdx.x) >> 5;

    // query row 0, lane's float4 slice (L2/L1 hit after first block)
    float4 q4 = reinterpret_cast<const float4*>(q)[lane];
    float qsq = q4.x * q4.x + q4.y * q4.y + q4.z * q4.z + q4.w * q4.w;
#pragma unroll
    for (int o = 16; o; o >>= 1) qsq += __shfl_xor_sync(0xffffffffu, qsq, o);
    const float qn = fmaxf(sqrtf(qsq), 1e-8f);

    if (warp >= C) return;
    const float4 e4 = reinterpret_cast<const float4*>(emb + (size_t)warp * HDIM)[lane];
    float dot = q4.x * e4.x + q4.y * e4.y + q4.z * e4.z + q4.w * e4.w;
    float esq = e4.x * e4.x + e4.y * e4.y + e4.z * e4.z + e4.w * e4.w;
#pragma unroll
    for (int o = 16; o; o >>= 1) {
        dot += __shfl_xor_sync(0xffffffffu, dot, o);
        esq += __shfl_xor_sync(0xffffffffu, esq, o);
    }
    if (lane == 0) {
        const float en = fmaxf(sqrtf(esq), 1e-8f);
        g_sims[warp] = dot / (qn * en);
    }
}

// ---------------------------------------------------------------------------
// Top-K building blocks
// ---------------------------------------------------------------------------
__device__ __forceinline__ void insert_topk(float* lv, int* li, float v, int c) {
    if (better(v, c, lv[KTOP - 1], li[KTOP - 1])) {
        int j = KTOP - 1;
#pragma unroll
        for (; j > 0; --j) {
            if (better(v, c, lv[j - 1], li[j - 1])) {
                lv[j] = lv[j - 1];
                li[j] = li[j - 1];
            } else break;
        }
        lv[j] = v;
        li[j] = c;
    }
}

// Merge-reduce 256 per-thread sorted top-K lists in shared memory -> slot 0
__device__ __forceinline__ void block_merge_topk(float* sv, int* si) {
    const int t = threadIdx.x;
    for (int s = 128; s > 0; s >>= 1) {
        if (t < s) {
            float mv[KTOP];
            int   mi[KTOP];
            int a = 0, b = 0;
#pragma unroll
            for (int j = 0; j < KTOP; ++j) {
                float va = sv[t * KTOP + a];       int ia = si[t * KTOP + a];
                float vb = sv[(t + s) * KTOP + b]; int ib = si[(t + s) * KTOP + b];
                if (better(va, ia, vb, ib)) { mv[j] = va; mi[j] = ia; ++a; }
                else                        { mv[j] = vb; mi[j] = ib; ++b; }
            }
#pragma unroll
            for (int j = 0; j < KTOP; ++j) {
                sv[t * KTOP + j] = mv[j];
                si[t * KTOP + j] = mi[j];
            }
        }
        __syncthreads();
    }
}

// Stage 1: each of NB1 blocks produces a top-8 of its strided slice.
__global__ void topk_stage1(int C) {
    __shared__ float sv[256 * KTOP];
    __shared__ int   si[256 * KTOP];
    const int t = threadIdx.x;

    float lv[KTOP];
    int   li[KTOP];
#pragma unroll
    for (int j = 0; j < KTOP; ++j) { lv[j] = -INFINITY; li[j] = INT_MAX; }

    for (int c = blockIdx.x * blockDim.x + t; c < C; c += gridDim.x * blockDim.x)
        insert_topk(lv, li, g_sims[c], c);

#pragma unroll
    for (int j = 0; j < KTOP; ++j) { sv[t * KTOP + j] = lv[j]; si[t * KTOP + j] = li[j]; }
    __syncthreads();
    block_merge_topk(sv, si);

    if (t < KTOP) {
        g_cand_v[blockIdx.x * KTOP + t] = sv[t];
        g_cand_i[blockIdx.x * KTOP + t] = si[t];
    }
}

// Stage 2: single block merges NB1*KTOP = 1024 candidates -> global top-8.
__global__ void topk_stage2() {
    __shared__ float sv[256 * KTOP];
    __shared__ int   si[256 * KTOP];
    const int t = threadIdx.x;

    float lv[KTOP];
    int   li[KTOP];
#pragma unroll
    for (int j = 0; j < KTOP; ++j) { lv[j] = -INFINITY; li[j] = INT_MAX; }

    for (int c = t; c < NB1 * KTOP; c += 256)
        insert_topk(lv, li, g_cand_v[c], g_cand_i[c]);

#pragma unroll
    for (int j = 0; j < KTOP; ++j) { sv[t * KTOP + j] = lv[j]; si[t * KTOP + j] = li[j]; }
    __syncthreads();
    block_merge_topk(sv, si);

    if (t < KTOP) {
        g_top_v[t] = sv[t];
        g_top_i[t] = si[t];
    }
}

// ---------------------------------------------------------------------------
// Kernel C: gather the top-8 episodes [8,32,128] + append the 8 scores.
// Output layout: retrieved (8*32*128 floats) followed by top_scores (8 floats).
// ---------------------------------------------------------------------------
__global__ void gather_kernel(const float* __restrict__ episodes,
                              float* __restrict__ out) {
    const int e = blockIdx.x;                 // 0..7
    const int idx = g_top_i[e];
    const float4* __restrict__ src =
        reinterpret_cast<const float4*>(episodes + (size_t)idx * (SDIM * HDIM));
    float4* __restrict__ dst =
        reinterpret_cast<float4*>(out + (size_t)e * (SDIM * HDIM));
    const int n4 = SDIM * HDIM / 4;           // 1024
    for (int i = threadIdx.x; i < n4; i += blockDim.x) dst[i] = src[i];

    if (e == 0 && threadIdx.x < KTOP)
        out[KTOP * SDIM * HDIM + threadIdx.x] = g_top_v[threadIdx.x];
}

extern "C" void kernel_launch(void* const* d_in, const int* in_sizes, int n_in,
                              void* d_out, int out_size) {
    const float* query    = (const float*)d_in[0];  // [B, 128]
    const float* episodes = (const float*)d_in[1];  // [C, 32, 128]
    const float* emb      = (const float*)d_in[2];  // [C, 128]
    (void)n_in; (void)out_size;

    const int C = in_sizes[2] / HDIM;               // 100000

    // A: cosine sims (warp per embedding, 8 warps/block)
    const int threadsA = 256;
    const int warpsPerBlock = threadsA / 32;
    const int blocksA = (C + warpsPerBlock - 1) / warpsPerBlock;
    sims_kernel<<<blocksA, threadsA>>>(query, emb, C);

    // B: two-stage top-8
    topk_stage1<<<NB1, 256>>>(C);
    topk_stage2<<<1, 256>>>();

    // C: gather + scores
    gather_kernel<<<KTOP, 256>>>(episodes, (float*)d_out);
}